// round 1
// baseline (speedup 1.0000x reference)
#include <cuda_runtime.h>
#include <cuda_bf16.h>
#include <mma.h>

using namespace nvcuda;

#define T_DIM 2048
#define S_DIM 2048
#define B_DIM 4
#define H_DIM 8
#define D_DIM 64
#define HIDW 256
#define NOUT 512
#define NROWS (T_DIM*B_DIM)

// scratch (device globals; no allocation allowed)
__device__ __align__(128) __nv_bfloat16 g_qkv[3][(size_t)NROWS*NOUT];
__device__ __align__(128) float g_ctx[(size_t)NROWS*NOUT];

// ---------------------------------------------------------------------------
// Kernel 1: fused 2-layer MLP projection (tf32 wmma), outputs bf16 [r][512]
// r = s*B + b row ordering (native to the [S,B,64] inputs)
// ---------------------------------------------------------------------------
#define XS_STRIDE 72
#define HID_STRIDE 264
#define PROJ_SMEM (64*XS_STRIDE*4 + 64*HID_STRIDE*4)

__global__ void proj_kernel(const float* __restrict__ x,
                            const float* __restrict__ W1, const float* __restrict__ b1,
                            const float* __restrict__ W2, const float* __restrict__ b2,
                            int out_idx, float scale)
{
    extern __shared__ float sm[];
    float* xs  = sm;                      // [64][72] fp32, reused as staging in phase 2
    float* hid = sm + 64*XS_STRIDE;       // [64][264] fp32
    __nv_bfloat16* outp = g_qkv[out_idx];

    int tid  = threadIdx.x;
    int w    = tid >> 5;
    int lane = tid & 31;
    int r0   = blockIdx.x * 64;

    // load x tile [64][64]
    {
        int r = tid >> 1, part = tid & 1;
        const float4* src = reinterpret_cast<const float4*>(&x[(size_t)(r0 + r)*64 + part*32]);
        float4* dst = reinterpret_cast<float4*>(&xs[r*XS_STRIDE + part*32]);
        #pragma unroll
        for (int i = 0; i < 8; i++) dst[i] = src[i];
    }
    __syncthreads();

    // phase 1: hid = x @ W1 (bias+relu applied after)
    #pragma unroll 1
    for (int ng = 0; ng < 4; ng++) {
        wmma::fragment<wmma::accumulator,16,16,8,float> acc[4];
        #pragma unroll
        for (int i = 0; i < 4; i++) wmma::fill_fragment(acc[i], 0.f);
        #pragma unroll 1
        for (int ks = 0; ks < 8; ks++) {
            wmma::fragment<wmma::matrix_a,16,16,8,wmma::precision::tf32,wmma::row_major> af;
            wmma::load_matrix_sync(af, &xs[w*16*XS_STRIDE + ks*8], XS_STRIDE);
            #pragma unroll
            for (int t = 0; t < af.num_elements; t++) af.x[t] = wmma::__float_to_tf32(af.x[t]);
            #pragma unroll
            for (int i = 0; i < 4; i++) {
                wmma::fragment<wmma::matrix_b,16,16,8,wmma::precision::tf32,wmma::row_major> bf;
                wmma::load_matrix_sync(bf, &W1[(size_t)ks*8*HIDW + (ng*4+i)*16], HIDW);
                #pragma unroll
                for (int t = 0; t < bf.num_elements; t++) bf.x[t] = wmma::__float_to_tf32(bf.x[t]);
                wmma::mma_sync(acc[i], af, bf, acc[i]);
            }
        }
        #pragma unroll
        for (int i = 0; i < 4; i++)
            wmma::store_matrix_sync(&hid[w*16*HID_STRIDE + (ng*4+i)*16], acc[i], HID_STRIDE, wmma::mem_row_major);
    }
    __syncthreads();
    // bias + relu
    for (int i = tid; i < 64*HIDW; i += 128) {
        int r = i >> 8, c = i & 255;
        float v = hid[r*HID_STRIDE + c] + b1[c];
        hid[r*HID_STRIDE + c] = v > 0.f ? v : 0.f;
    }
    __syncthreads();

    // phase 2: y = hid @ W2 + b2, optional scale, bf16 store
    float* stg = xs + w*(16*20);   // per-warp staging 16x20 fp32 (xs region is free now)
    #pragma unroll 1
    for (int ng = 0; ng < 8; ng++) {
        wmma::fragment<wmma::accumulator,16,16,8,float> acc[4];
        #pragma unroll
        for (int i = 0; i < 4; i++) wmma::fill_fragment(acc[i], 0.f);
        #pragma unroll 1
        for (int ks = 0; ks < 32; ks++) {
            wmma::fragment<wmma::matrix_a,16,16,8,wmma::precision::tf32,wmma::row_major> af;
            wmma::load_matrix_sync(af, &hid[w*16*HID_STRIDE + ks*8], HID_STRIDE);
            #pragma unroll
            for (int t = 0; t < af.num_elements; t++) af.x[t] = wmma::__float_to_tf32(af.x[t]);
            #pragma unroll
            for (int i = 0; i < 4; i++) {
                wmma::fragment<wmma::matrix_b,16,16,8,wmma::precision::tf32,wmma::row_major> bf;
                wmma::load_matrix_sync(bf, &W2[(size_t)ks*8*NOUT + (ng*4+i)*16], NOUT);
                #pragma unroll
                for (int t = 0; t < bf.num_elements; t++) bf.x[t] = wmma::__float_to_tf32(bf.x[t]);
                wmma::mma_sync(acc[i], af, bf, acc[i]);
            }
        }
        #pragma unroll 1
        for (int i = 0; i < 4; i++) {
            wmma::store_matrix_sync(stg, acc[i], 20, wmma::mem_row_major);
            __syncwarp();
            int n0  = (ng*4 + i)*16;
            int row = lane >> 1, half = lane & 1;
            union { uint4 u; __nv_bfloat16 hh[8]; } pk;
            #pragma unroll
            for (int j = 0; j < 8; j++) {
                int c = half*8 + j;
                float v = (stg[row*20 + c] + b2[n0 + c]) * scale;
                pk.hh[j] = __float2bfloat16(v);
            }
            *reinterpret_cast<uint4*>(&outp[(size_t)(r0 + w*16 + row)*NOUT + n0 + half*8]) = pk.u;
            __syncwarp();
        }
    }
}

// ---------------------------------------------------------------------------
// Kernel 2: flash attention (bf16 wmma), no max-subtraction (scores bounded),
// CTA = (b, h, 64 t-rows), 4 warps x 16-row bands, s-tiles of 64
// ---------------------------------------------------------------------------
#define AS 72
#define ATTN_SMEM (64*AS*2*3 + 64*AS*4 + 64*AS*2)

__global__ void attn_kernel(const float* __restrict__ mask)
{
    extern __shared__ char smc[];
    __nv_bfloat16* qs  = reinterpret_cast<__nv_bfloat16*>(smc);
    __nv_bfloat16* ksm = qs  + 64*AS;
    __nv_bfloat16* vsm = ksm + 64*AS;
    float*         sc  = reinterpret_cast<float*>(vsm + 64*AS);      // [64][72] fp32
    __nv_bfloat16* ps  = reinterpret_cast<__nv_bfloat16*>(sc + 64*AS); // [64][72] bf16

    int tid  = threadIdx.x;
    int w    = tid >> 5, lane = tid & 31;
    int t0   = blockIdx.x * 64;
    int h    = blockIdx.y, b = blockIdx.z;

    const __nv_bfloat16* qg = g_qkv[0];
    const __nv_bfloat16* kg = g_qkv[1];
    const __nv_bfloat16* vg = g_qkv[2];

    // load Q tile (already scaled by d^-0.5 at projection)
    {
        int r = tid >> 1, part = tid & 1;
        const uint4* src = reinterpret_cast<const uint4*>(
            &qg[(size_t)((t0 + r)*B_DIM + b)*NOUT + h*64 + part*32]);
        uint4* dst = reinterpret_cast<uint4*>(&qs[r*AS + part*32]);
        #pragma unroll
        for (int i = 0; i < 4; i++) dst[i] = src[i];
    }
    __syncthreads();

    wmma::fragment<wmma::matrix_a,16,16,16,__nv_bfloat16,wmma::row_major> qf[4];
    #pragma unroll
    for (int ks = 0; ks < 4; ks++)
        wmma::load_matrix_sync(qf[ks], &qs[w*16*AS + ks*16], AS);

    wmma::fragment<wmma::accumulator,16,16,16,float> accO[4];
    #pragma unroll
    for (int i = 0; i < 4; i++) wmma::fill_fragment(accO[i], 0.f);

    float lsum = 0.f;
    int row = lane >> 1, half = lane & 1;

    #pragma unroll 1
    for (int it = 0; it < S_DIM/64; it++) {
        int s0 = it * 64;
        __syncthreads();   // all warps done reading ksm/vsm from previous tile
        {
            int r = tid >> 1, part = tid & 1;
            const uint4* srck = reinterpret_cast<const uint4*>(
                &kg[(size_t)((s0 + r)*B_DIM + b)*NOUT + h*64 + part*32]);
            const uint4* srcv = reinterpret_cast<const uint4*>(
                &vg[(size_t)((s0 + r)*B_DIM + b)*NOUT + h*64 + part*32]);
            uint4* dk = reinterpret_cast<uint4*>(&ksm[r*AS + part*32]);
            uint4* dv = reinterpret_cast<uint4*>(&vsm[r*AS + part*32]);
            #pragma unroll
            for (int i = 0; i < 4; i++) { dk[i] = srck[i]; dv[i] = srcv[i]; }
        }
        __syncthreads();

        // scores: S = Q @ K^T  (16x64 per warp)
        #pragma unroll
        for (int n = 0; n < 4; n++) {
            wmma::fragment<wmma::accumulator,16,16,16,float> accS;
            wmma::fill_fragment(accS, 0.f);
            #pragma unroll
            for (int ks = 0; ks < 4; ks++) {
                wmma::fragment<wmma::matrix_b,16,16,16,__nv_bfloat16,wmma::col_major> kf;
                wmma::load_matrix_sync(kf, &ksm[(n*16)*AS + ks*16], AS);
                wmma::mma_sync(accS, qf[ks], kf, accS);
            }
            wmma::store_matrix_sync(&sc[(w*16)*AS + n*16], accS, AS, wmma::mem_row_major);
        }
        __syncwarp();

        // softmax numerator: p = exp(s + mask); accumulate l. No rescale needed.
        {
            const float* srow = &sc[(w*16 + row)*AS + half*32];
            const float* mrow = &mask[((size_t)b*T_DIM + (t0 + w*16 + row))*S_DIM + s0 + half*32];
            __nv_bfloat16* prow = &ps[(w*16 + row)*AS + half*32];
            #pragma unroll
            for (int jj = 0; jj < 32; jj += 4) {
                float4 s4 = *reinterpret_cast<const float4*>(&srow[jj]);
                float4 m4 = *reinterpret_cast<const float4*>(&mrow[jj]);
                float e0 = __expf(s4.x + m4.x);
                float e1 = __expf(s4.y + m4.y);
                float e2 = __expf(s4.z + m4.z);
                float e3 = __expf(s4.w + m4.w);
                lsum += (e0 + e1) + (e2 + e3);
                union { uint2 u; __nv_bfloat16 hh[4]; } pk;
                pk.hh[0] = __float2bfloat16(e0);
                pk.hh[1] = __float2bfloat16(e1);
                pk.hh[2] = __float2bfloat16(e2);
                pk.hh[3] = __float2bfloat16(e3);
                *reinterpret_cast<uint2*>(&prow[jj]) = pk.u;
            }
        }
        __syncwarp();

        // O += P @ V
        wmma::fragment<wmma::matrix_a,16,16,16,__nv_bfloat16,wmma::row_major> paf[4];
        #pragma unroll
        for (int ks = 0; ks < 4; ks++)
            wmma::load_matrix_sync(paf[ks], &ps[w*16*AS + ks*16], AS);
        #pragma unroll
        for (int n = 0; n < 4; n++) {
            #pragma unroll
            for (int ks = 0; ks < 4; ks++) {
                wmma::fragment<wmma::matrix_b,16,16,16,__nv_bfloat16,wmma::row_major> vf;
                wmma::load_matrix_sync(vf, &vsm[(ks*16)*AS + n*16], AS);
                wmma::mma_sync(accO[n], paf[ks], vf, accO[n]);
            }
        }
    }

    // epilogue: divide by l, write ctx [r][512] (r = t*B + b)
    float l = lsum + __shfl_xor_sync(0xffffffffu, lsum, 1);
    float inv = 1.f / l;
    #pragma unroll
    for (int n = 0; n < 4; n++)
        wmma::store_matrix_sync(&sc[w*16*AS + n*16], accO[n], AS, wmma::mem_row_major);
    __syncwarp();
    {
        float* orow = &g_ctx[(size_t)((t0 + w*16 + row)*B_DIM + b)*NOUT + h*64 + half*32];
        const float* srow = &sc[(w*16 + row)*AS + half*32];
        #pragma unroll
        for (int jj = 0; jj < 32; jj += 4) {
            float4 v4 = *reinterpret_cast<const float4*>(&srow[jj]);
            v4.x *= inv; v4.y *= inv; v4.z *= inv; v4.w *= inv;
            *reinterpret_cast<float4*>(&orow[jj]) = v4;
        }
    }
}

// ---------------------------------------------------------------------------
// Kernel 3: out = ctx @ Wo + bo  (fp32; 0.27 GFLOP, memory-trivial)
// ---------------------------------------------------------------------------
__global__ void outproj_kernel(const float* __restrict__ Wo, const float* __restrict__ bo,
                               float* __restrict__ out)
{
    __shared__ float ctxT[64][68];
    int tid = threadIdx.x;
    int r0  = blockIdx.x * 64;
    int j   = tid & 63, rg = tid >> 6;
    float acc[16];
    #pragma unroll
    for (int i = 0; i < 16; i++) acc[i] = 0.f;

    #pragma unroll 1
    for (int kt = 0; kt < 8; kt++) {
        if (kt) __syncthreads();
        {
            int r = tid >> 2, q = tid & 3;
            #pragma unroll
            for (int i = 0; i < 4; i++) {
                int k = q*16 + i*4;
                float4 v4 = *reinterpret_cast<const float4*>(
                    &g_ctx[(size_t)(r0 + r)*NOUT + kt*64 + k]);
                ctxT[k+0][r] = v4.x;
                ctxT[k+1][r] = v4.y;
                ctxT[k+2][r] = v4.z;
                ctxT[k+3][r] = v4.w;
            }
        }
        __syncthreads();
        #pragma unroll 4
        for (int k = 0; k < 64; k++) {
            float wv = Wo[(size_t)(kt*64 + k)*64 + j];
            #pragma unroll
            for (int rr = 0; rr < 16; rr += 4) {
                float4 c4 = *reinterpret_cast<const float4*>(&ctxT[k][rg*16 + rr]);
                acc[rr+0] += wv * c4.x;
                acc[rr+1] += wv * c4.y;
                acc[rr+2] += wv * c4.z;
                acc[rr+3] += wv * c4.w;
            }
        }
    }
    float bj = bo[j];
    #pragma unroll
    for (int rr = 0; rr < 16; rr++)
        out[(size_t)(r0 + rg*16 + rr)*64 + j] = acc[rr] + bj;
}

// ---------------------------------------------------------------------------
extern "C" void kernel_launch(void* const* d_in, const int* in_sizes, int n_in,
                              void* d_out, int out_size)
{
    const float* query = (const float*)d_in[0];
    const float* key   = (const float*)d_in[1];
    const float* value = (const float*)d_in[2];
    const float* mask  = (const float*)d_in[3];
    const float* Wq1 = (const float*)d_in[4];
    const float* bq1 = (const float*)d_in[5];
    const float* Wq2 = (const float*)d_in[6];
    const float* bq2 = (const float*)d_in[7];
    const float* Wk1 = (const float*)d_in[8];
    const float* bk1 = (const float*)d_in[9];
    const float* Wk2 = (const float*)d_in[10];
    const float* bk2 = (const float*)d_in[11];
    const float* Wv1 = (const float*)d_in[12];
    const float* bv1 = (const float*)d_in[13];
    const float* Wv2 = (const float*)d_in[14];
    const float* bv2 = (const float*)d_in[15];
    const float* Wo  = (const float*)d_in[16];
    const float* bo  = (const float*)d_in[17];
    float* out = (float*)d_out;

    cudaFuncSetAttribute(proj_kernel, cudaFuncAttributeMaxDynamicSharedMemorySize, PROJ_SMEM);
    cudaFuncSetAttribute(attn_kernel, cudaFuncAttributeMaxDynamicSharedMemorySize, ATTN_SMEM);

    proj_kernel<<<128, 128, PROJ_SMEM>>>(query, Wq1, bq1, Wq2, bq2, 0, 0.125f);
    proj_kernel<<<128, 128, PROJ_SMEM>>>(key,   Wk1, bk1, Wk2, bk2, 1, 1.0f);
    proj_kernel<<<128, 128, PROJ_SMEM>>>(value, Wv1, bv1, Wv2, bv2, 2, 1.0f);
    attn_kernel<<<dim3(32, 8, 4), 128, ATTN_SMEM>>>(mask);
    outproj_kernel<<<128, 256>>>(Wo, bo, out);
}

// round 2
// speedup vs baseline: 3.0509x; 3.0509x over previous
#include <cuda_runtime.h>
#include <cuda_bf16.h>
#include <mma.h>
#include <cstdint>

using namespace nvcuda;

#define T_DIM 2048
#define S_DIM 2048
#define B_DIM 4
#define H_DIM 8
#define NOUT 512
#define NROWS (T_DIM*B_DIM)

// scratch (device globals; no allocation allowed)
__device__ __align__(128) __nv_bfloat16 g_qkv[3][(size_t)NROWS*NOUT];
__device__ __align__(128) float g_ctx[(size_t)NROWS*NOUT];

// ---------------------------------------------------------------------------
// helpers
// ---------------------------------------------------------------------------
__device__ __forceinline__ uint32_t smem_u32(const void* p) {
    return (uint32_t)__cvta_generic_to_shared(p);
}
__device__ __forceinline__ uint32_t pkbf(float a, float b) {
    __nv_bfloat162 t = __floats2bfloat162_rn(a, b);
    return *reinterpret_cast<uint32_t*>(&t);
}
__device__ __forceinline__ void ldmx4(uint32_t& r0, uint32_t& r1, uint32_t& r2, uint32_t& r3, uint32_t a) {
    asm volatile("ldmatrix.sync.aligned.m8n8.x4.shared.b16 {%0,%1,%2,%3}, [%4];"
                 : "=r"(r0), "=r"(r1), "=r"(r2), "=r"(r3) : "r"(a));
}
__device__ __forceinline__ void ldmx2(uint32_t& r0, uint32_t& r1, uint32_t a) {
    asm volatile("ldmatrix.sync.aligned.m8n8.x2.shared.b16 {%0,%1}, [%2];"
                 : "=r"(r0), "=r"(r1) : "r"(a));
}
__device__ __forceinline__ void ldmx2t(uint32_t& r0, uint32_t& r1, uint32_t a) {
    asm volatile("ldmatrix.sync.aligned.m8n8.x2.trans.shared.b16 {%0,%1}, [%2];"
                 : "=r"(r0), "=r"(r1) : "r"(a));
}
__device__ __forceinline__ void mma_bf16(float& c0, float& c1, float& c2, float& c3,
                                         const uint32_t a[4], uint32_t b0, uint32_t b1) {
    asm volatile("mma.sync.aligned.m16n8k16.row.col.f32.bf16.bf16.f32 "
                 "{%0,%1,%2,%3}, {%4,%5,%6,%7}, {%8,%9}, {%0,%1,%2,%3};"
                 : "+f"(c0), "+f"(c1), "+f"(c2), "+f"(c3)
                 : "r"(a[0]), "r"(a[1]), "r"(a[2]), "r"(a[3]), "r"(b0), "r"(b1));
}
__device__ __forceinline__ void cp16(uint32_t dst, const void* src) {
    asm volatile("cp.async.cg.shared.global [%0], [%1], 16;" :: "r"(dst), "l"(src));
}
__device__ __forceinline__ void cp_commit() { asm volatile("cp.async.commit_group;"); }
__device__ __forceinline__ void cp_wait1()  { asm volatile("cp.async.wait_group 1;"); }
__device__ __forceinline__ void cp_wait0()  { asm volatile("cp.async.wait_group 0;"); }

// ---------------------------------------------------------------------------
// Kernel 1: combined QKV MLP. Phase1 bf16 wmma (X@W1, relu), phase2 tf32 wmma
// (H@W2). 128 rows/CTA, 8 warps. Weights staged in smem.
// ---------------------------------------------------------------------------
struct ProjAll {
    const float* x[3];
    const float* W1[3]; const float* b1[3];
    const float* W2[3]; const float* b2[3];
    float scale[3];
};

#define HST 260
#define PROJ_SMEM (128*HST*4 + 69632)

__global__ void __launch_bounds__(256) proj_kernel(ProjAll P)
{
    extern __shared__ char sm[];
    float* Hs = reinterpret_cast<float*>(sm);                 // [128][260] fp32
    char* U = sm + 128*HST*4;
    __nv_bfloat16* Xs  = reinterpret_cast<__nv_bfloat16*>(U);          // [128][72] bf16
    __nv_bfloat16* W1s = reinterpret_cast<__nv_bfloat16*>(U + 18432);  // [64][264] bf16
    float* W2s = reinterpret_cast<float*>(U);                 // [256][68] fp32 (phase2)
    float* stg = reinterpret_cast<float*>(U);                 // [128][68] staging

    int pid = blockIdx.y;
    const float* x  = P.x[pid];
    const float* W1 = P.W1[pid]; const float* b1 = P.b1[pid];
    const float* W2 = P.W2[pid]; const float* b2 = P.b2[pid];
    float scale = P.scale[pid];
    __nv_bfloat16* outp = g_qkv[pid];

    int tid = threadIdx.x, w = tid >> 5;
    int r0 = blockIdx.x * 128;
    int wr = w >> 1, wc = w & 1;

    // load X tile [128][64] fp32 -> bf16 smem
    {
        int r = tid >> 1, c0 = (tid & 1) * 32;
        const float4* src = reinterpret_cast<const float4*>(&x[(size_t)(r0 + r)*64 + c0]);
        __nv_bfloat162 tmp[16];
        #pragma unroll
        for (int i = 0; i < 8; i++) {
            float4 v = src[i];
            tmp[2*i]   = __floats2bfloat162_rn(v.x, v.y);
            tmp[2*i+1] = __floats2bfloat162_rn(v.z, v.w);
        }
        uint4* dst = reinterpret_cast<uint4*>(&Xs[r*72 + c0]);
        const uint4* ts = reinterpret_cast<const uint4*>(tmp);
        dst[0] = ts[0]; dst[1] = ts[1]; dst[2] = ts[2]; dst[3] = ts[3];
    }
    // load W1 [64][256] fp32 -> bf16 smem
    for (int i = tid; i < 4096; i += 256) {
        int row = i >> 6, c4 = i & 63;
        float4 v = *reinterpret_cast<const float4*>(&W1[(size_t)row*256 + c4*4]);
        __nv_bfloat162 p0 = __floats2bfloat162_rn(v.x, v.y);
        __nv_bfloat162 p1 = __floats2bfloat162_rn(v.z, v.w);
        uint2 u; u.x = *reinterpret_cast<uint32_t*>(&p0); u.y = *reinterpret_cast<uint32_t*>(&p1);
        *reinterpret_cast<uint2*>(&W1s[row*264 + c4*4]) = u;
    }
    __syncthreads();

    // phase1: H = X @ W1 (bf16 wmma, fp32 acc)
    #pragma unroll 1
    for (int nc = 0; nc < 4; nc++) {
        int col = nc*64 + wc*32;
        wmma::fragment<wmma::accumulator,16,16,16,float> acc[2][2];
        #pragma unroll
        for (int i = 0; i < 2; i++)
            #pragma unroll
            for (int j = 0; j < 2; j++) wmma::fill_fragment(acc[i][j], 0.f);
        #pragma unroll
        for (int kc = 0; kc < 4; kc++) {
            wmma::fragment<wmma::matrix_a,16,16,16,__nv_bfloat16,wmma::row_major> af[2];
            #pragma unroll
            for (int i = 0; i < 2; i++)
                wmma::load_matrix_sync(af[i], &Xs[(wr*32 + i*16)*72 + kc*16], 72);
            #pragma unroll
            for (int j = 0; j < 2; j++) {
                wmma::fragment<wmma::matrix_b,16,16,16,__nv_bfloat16,wmma::row_major> bf;
                wmma::load_matrix_sync(bf, &W1s[(kc*16)*264 + col + j*16], 264);
                wmma::mma_sync(acc[0][j], af[0], bf, acc[0][j]);
                wmma::mma_sync(acc[1][j], af[1], bf, acc[1][j]);
            }
        }
        #pragma unroll
        for (int i = 0; i < 2; i++)
            #pragma unroll
            for (int j = 0; j < 2; j++)
                wmma::store_matrix_sync(&Hs[(wr*32 + i*16)*HST + col + j*16], acc[i][j], HST, wmma::mem_row_major);
    }
    __syncthreads();
    // bias + relu
    for (int i = tid; i < 8192; i += 256) {
        int r = i >> 6, c4 = i & 63;
        float4 v = *reinterpret_cast<float4*>(&Hs[r*HST + c4*4]);
        float4 bb = *reinterpret_cast<const float4*>(&b1[c4*4]);
        v.x = fmaxf(v.x + bb.x, 0.f); v.y = fmaxf(v.y + bb.y, 0.f);
        v.z = fmaxf(v.z + bb.z, 0.f); v.w = fmaxf(v.w + bb.w, 0.f);
        *reinterpret_cast<float4*>(&Hs[r*HST + c4*4]) = v;
    }

    // phase2: Y = H @ W2, tf32 wmma, n-chunks of 64
    #pragma unroll 1
    for (int nc = 0; nc < 8; nc++) {
        __syncthreads();   // prior users of U done
        for (int i = tid; i < 4096; i += 256) {
            int k = i >> 4, c4 = i & 15;
            *reinterpret_cast<float4*>(&W2s[k*68 + c4*4]) =
                *reinterpret_cast<const float4*>(&W2[(size_t)k*512 + nc*64 + c4*4]);
        }
        __syncthreads();

        wmma::fragment<wmma::accumulator,16,16,8,float> acc[2][2];
        #pragma unroll
        for (int i = 0; i < 2; i++)
            #pragma unroll
            for (int j = 0; j < 2; j++) wmma::fill_fragment(acc[i][j], 0.f);
        #pragma unroll 1
        for (int ks = 0; ks < 32; ks++) {
            wmma::fragment<wmma::matrix_a,16,16,8,wmma::precision::tf32,wmma::row_major> af[2];
            #pragma unroll
            for (int i = 0; i < 2; i++) {
                wmma::load_matrix_sync(af[i], &Hs[(wr*32 + i*16)*HST + ks*8], HST);
                #pragma unroll
                for (int t = 0; t < af[i].num_elements; t++) af[i].x[t] = wmma::__float_to_tf32(af[i].x[t]);
            }
            #pragma unroll
            for (int j = 0; j < 2; j++) {
                wmma::fragment<wmma::matrix_b,16,16,8,wmma::precision::tf32,wmma::row_major> bf;
                wmma::load_matrix_sync(bf, &W2s[(ks*8)*68 + wc*32 + j*16], 68);
                #pragma unroll
                for (int t = 0; t < bf.num_elements; t++) bf.x[t] = wmma::__float_to_tf32(bf.x[t]);
                wmma::mma_sync(acc[0][j], af[0], bf, acc[0][j]);
                wmma::mma_sync(acc[1][j], af[1], bf, acc[1][j]);
            }
        }
        __syncthreads();   // all done reading W2s
        #pragma unroll
        for (int i = 0; i < 2; i++)
            #pragma unroll
            for (int j = 0; j < 2; j++)
                wmma::store_matrix_sync(&stg[(wr*32 + i*16)*68 + wc*32 + j*16], acc[i][j], 68, wmma::mem_row_major);
        __syncthreads();
        // bias + scale + bf16 store
        {
            int r = tid >> 1, half = tid & 1;
            int cb = nc*64 + half*32;
            __nv_bfloat162 ob[16];
            #pragma unroll
            for (int j = 0; j < 32; j += 2) {
                float v0 = (stg[r*68 + half*32 + j]     + b2[cb + j])     * scale;
                float v1 = (stg[r*68 + half*32 + j + 1] + b2[cb + j + 1]) * scale;
                ob[j >> 1] = __floats2bfloat162_rn(v0, v1);
            }
            uint4* dst = reinterpret_cast<uint4*>(&outp[(size_t)(r0 + r)*512 + cb]);
            const uint4* os = reinterpret_cast<const uint4*>(ob);
            dst[0] = os[0]; dst[1] = os[1]; dst[2] = os[2]; dst[3] = os[3];
        }
    }
}

// ---------------------------------------------------------------------------
// Kernel 2: flash attention, raw mma.m16n8k16, scores in registers,
// cp.async double-buffered K/V. CTA = (b,h,64 t-rows), 4 warps x 16 rows.
// ---------------------------------------------------------------------------
__global__ void __launch_bounds__(128, 4) attn_kernel(const float* __restrict__ mask)
{
    __shared__ __nv_bfloat16 Qs[64*72];
    __shared__ __nv_bfloat16 Ks[2][64*72];
    __shared__ __nv_bfloat16 Vs[2][64*72];

    int tid = threadIdx.x, w = tid >> 5, lane = tid & 31;
    int t0 = blockIdx.x * 64, h = blockIdx.y, b = blockIdx.z;
    const __nv_bfloat16* qg = g_qkv[0];
    const __nv_bfloat16* kg = g_qkv[1];
    const __nv_bfloat16* vg = g_qkv[2];

    // load Q tile
    {
        int r = tid >> 1, part = tid & 1;
        const uint4* src = reinterpret_cast<const uint4*>(
            &qg[((size_t)(t0 + r)*B_DIM + b)*NOUT + h*64 + part*32]);
        uint4* dst = reinterpret_cast<uint4*>(&Qs[r*72 + part*32]);
        dst[0] = src[0]; dst[1] = src[1]; dst[2] = src[2]; dst[3] = src[3];
    }

    // K/V cp.async staging pointers for this thread
    int lr = tid >> 1, lpart = tid & 1;
    const __nv_bfloat16* kbase = &kg[((size_t)lr*B_DIM + b)*NOUT + h*64 + lpart*32];
    const __nv_bfloat16* vbase = &vg[((size_t)lr*B_DIM + b)*NOUT + h*64 + lpart*32];
    uint32_t dK0 = smem_u32(&Ks[0][lr*72 + lpart*32]);
    uint32_t dV0 = smem_u32(&Vs[0][lr*72 + lpart*32]);
    const uint32_t bufstride = 64*72*2;  // bytes per buffer

    // issue tile it into buffer
    auto issue = [&](int it, int buf) {
        size_t off = (size_t)it * 64 * B_DIM * NOUT;
        const char* sK = reinterpret_cast<const char*>(kbase + off);
        const char* sV = reinterpret_cast<const char*>(vbase + off);
        uint32_t dK = dK0 + buf*bufstride, dV = dV0 + buf*bufstride;
        #pragma unroll
        for (int i = 0; i < 4; i++) {
            cp16(dK + i*16, sK + i*16);
            cp16(dV + i*16, sV + i*16);
        }
        cp_commit();
    };

    issue(0, 0);
    __syncthreads();   // Qs ready

    // Q fragments (persist whole kernel)
    uint32_t qf[4][4];
    {
        int g2 = lane >> 3;
        #pragma unroll
        for (int kc = 0; kc < 4; kc++) {
            uint32_t a = smem_u32(&Qs[(w*16 + (lane & 7) + (g2 & 1)*8)*72 + kc*16 + (g2 >> 1)*8]);
            ldmx4(qf[kc][0], qf[kc][1], qf[kc][2], qf[kc][3], a);
        }
    }

    float accO[8][4];
    #pragma unroll
    for (int d = 0; d < 8; d++)
        #pragma unroll
        for (int i = 0; i < 4; i++) accO[d][i] = 0.f;

    float lsum_lo = 0.f, lsum_hi = 0.f;
    const float* mbase = mask + ((size_t)b*T_DIM + (t0 + w*16 + (lane >> 2)))*S_DIM + (lane & 3)*2;
    int lg = (lane >> 3) & 1, l7 = lane & 7;

    #pragma unroll 1
    for (int it = 0; it < S_DIM/64; it++) {
        if (it + 1 < S_DIM/64) { issue(it + 1, (it + 1) & 1); cp_wait1(); }
        else                   { cp_wait0(); }
        __syncthreads();
        int buf = it & 1;
        int s0 = it * 64;

        // S = Q @ K^T, +mask, exp -> P fragments (registers)
        uint32_t pa[4][4];
        #pragma unroll
        for (int n = 0; n < 8; n++) {
            float c0 = 0.f, c1 = 0.f, c2 = 0.f, c3 = 0.f;
            #pragma unroll
            for (int kc = 0; kc < 4; kc++) {
                uint32_t b0, b1;
                uint32_t a = smem_u32(&Ks[buf][(n*8 + l7)*72 + kc*16 + lg*8]);
                ldmx2(b0, b1, a);
                mma_bf16(c0, c1, c2, c3, qf[kc], b0, b1);
            }
            const float* mp = mbase + s0 + n*8;
            float2 m0 = *reinterpret_cast<const float2*>(mp);
            float2 m1 = *reinterpret_cast<const float2*>(mp + 8*(size_t)S_DIM);
            float e0 = __expf(c0 + m0.x), e1 = __expf(c1 + m0.y);
            float e2 = __expf(c2 + m1.x), e3 = __expf(c3 + m1.y);
            lsum_lo += e0 + e1;
            lsum_hi += e2 + e3;
            pa[n >> 1][(n & 1)*2 + 0] = pkbf(e0, e1);
            pa[n >> 1][(n & 1)*2 + 1] = pkbf(e2, e3);
        }

        // O += P @ V
        #pragma unroll
        for (int d = 0; d < 8; d++) {
            #pragma unroll
            for (int kc = 0; kc < 4; kc++) {
                uint32_t b0, b1;
                uint32_t a = smem_u32(&Vs[buf][(kc*16 + lg*8 + l7)*72 + d*8]);
                ldmx2t(b0, b1, a);
                mma_bf16(accO[d][0], accO[d][1], accO[d][2], accO[d][3], pa[kc], b0, b1);
            }
        }
        __syncthreads();
    }

    // reduce row sums across quads
    lsum_lo += __shfl_xor_sync(0xffffffffu, lsum_lo, 1);
    lsum_lo += __shfl_xor_sync(0xffffffffu, lsum_lo, 2);
    lsum_hi += __shfl_xor_sync(0xffffffffu, lsum_hi, 1);
    lsum_hi += __shfl_xor_sync(0xffffffffu, lsum_hi, 2);
    float inv_lo = 1.f / lsum_lo, inv_hi = 1.f / lsum_hi;

    int row = t0 + w*16 + (lane >> 2);
    float* o_lo = &g_ctx[((size_t)row*B_DIM + b)*NOUT + h*64 + (lane & 3)*2];
    float* o_hi = o_lo + (size_t)8*B_DIM*NOUT;
    #pragma unroll
    for (int d = 0; d < 8; d++) {
        float2 vlo = { accO[d][0]*inv_lo, accO[d][1]*inv_lo };
        float2 vhi = { accO[d][2]*inv_hi, accO[d][3]*inv_hi };
        *reinterpret_cast<float2*>(o_lo + d*8) = vlo;
        *reinterpret_cast<float2*>(o_hi + d*8) = vhi;
    }
}

// ---------------------------------------------------------------------------
// Kernel 3: out = ctx @ Wo + bo  (fp32)
// ---------------------------------------------------------------------------
__global__ void outproj_kernel(const float* __restrict__ Wo, const float* __restrict__ bo,
                               float* __restrict__ out)
{
    __shared__ float ctxT[64][68];
    int tid = threadIdx.x;
    int r0  = blockIdx.x * 64;
    int j   = tid & 63, rg = tid >> 6;
    float acc[16];
    #pragma unroll
    for (int i = 0; i < 16; i++) acc[i] = 0.f;

    #pragma unroll 1
    for (int kt = 0; kt < 8; kt++) {
        if (kt) __syncthreads();
        {
            int r = tid >> 2, q = tid & 3;
            #pragma unroll
            for (int i = 0; i < 4; i++) {
                int k = q*16 + i*4;
                float4 v4 = *reinterpret_cast<const float4*>(
                    &g_ctx[(size_t)(r0 + r)*NOUT + kt*64 + k]);
                ctxT[k+0][r] = v4.x;
                ctxT[k+1][r] = v4.y;
                ctxT[k+2][r] = v4.z;
                ctxT[k+3][r] = v4.w;
            }
        }
        __syncthreads();
        #pragma unroll 4
        for (int k = 0; k < 64; k++) {
            float wv = Wo[(size_t)(kt*64 + k)*64 + j];
            #pragma unroll
            for (int rr = 0; rr < 16; rr += 4) {
                float4 c4 = *reinterpret_cast<const float4*>(&ctxT[k][rg*16 + rr]);
                acc[rr+0] += wv * c4.x;
                acc[rr+1] += wv * c4.y;
                acc[rr+2] += wv * c4.z;
                acc[rr+3] += wv * c4.w;
            }
        }
    }
    float bj = bo[j];
    #pragma unroll
    for (int rr = 0; rr < 16; rr++)
        out[(size_t)(r0 + rg*16 + rr)*64 + j] = acc[rr] + bj;
}

// ---------------------------------------------------------------------------
extern "C" void kernel_launch(void* const* d_in, const int* in_sizes, int n_in,
                              void* d_out, int out_size)
{
    const float* query = (const float*)d_in[0];
    const float* key   = (const float*)d_in[1];
    const float* value = (const float*)d_in[2];
    const float* mask  = (const float*)d_in[3];
    ProjAll P;
    P.x[0] = query; P.x[1] = key; P.x[2] = value;
    P.W1[0] = (const float*)d_in[4];  P.b1[0] = (const float*)d_in[5];
    P.W2[0] = (const float*)d_in[6];  P.b2[0] = (const float*)d_in[7];
    P.W1[1] = (const float*)d_in[8];  P.b1[1] = (const float*)d_in[9];
    P.W2[1] = (const float*)d_in[10]; P.b2[1] = (const float*)d_in[11];
    P.W1[2] = (const float*)d_in[12]; P.b1[2] = (const float*)d_in[13];
    P.W2[2] = (const float*)d_in[14]; P.b2[2] = (const float*)d_in[15];
    P.scale[0] = 0.125f; P.scale[1] = 1.0f; P.scale[2] = 1.0f;
    const float* Wo  = (const float*)d_in[16];
    const float* bo  = (const float*)d_in[17];
    float* out = (float*)d_out;

    cudaFuncSetAttribute(proj_kernel, cudaFuncAttributeMaxDynamicSharedMemorySize, PROJ_SMEM);

    proj_kernel<<<dim3(64, 3), 256, PROJ_SMEM>>>(P);
    attn_kernel<<<dim3(32, 8, 4), 128>>>(mask);
    outproj_kernel<<<128, 256>>>(Wo, bo, out);
}

// round 6
// speedup vs baseline: 4.7065x; 1.5427x over previous
#include <cuda_runtime.h>
#include <cuda_bf16.h>
#include <cstdint>

#define T_DIM 2048
#define S_DIM 2048
#define B_DIM 4
#define H_DIM 8
#define NOUT 512
#define HIDW 256
#define NROWS (T_DIM*B_DIM)

// scratch (device globals; no allocation allowed)
__device__ __align__(128) __nv_bfloat16 g_qkv[3][(size_t)NROWS*NOUT];
__device__ __align__(128) float g_ctx[(size_t)NROWS*NOUT];
__device__ __align__(128) __nv_bfloat16 g_hid[3][(size_t)NROWS*HIDW];
__device__ __align__(128) __nv_bfloat16 g_w1h[3][64*HIDW];
__device__ __align__(128) __nv_bfloat16 g_w1l[64*HIDW];
__device__ __align__(128) __nv_bfloat16 g_w2h[3][HIDW*NOUT];
__device__ __align__(128) __nv_bfloat16 g_w2l[HIDW*NOUT];

// ---------------------------------------------------------------------------
// helpers
// ---------------------------------------------------------------------------
__device__ __forceinline__ uint32_t smem_u32(const void* p) {
    return (uint32_t)__cvta_generic_to_shared(p);
}
__device__ __forceinline__ uint32_t pkbf(float a, float b) {
    __nv_bfloat162 t = __floats2bfloat162_rn(a, b);
    return *reinterpret_cast<uint32_t*>(&t);
}
__device__ __forceinline__ void ldmx4(uint32_t& r0, uint32_t& r1, uint32_t& r2, uint32_t& r3, uint32_t a) {
    asm volatile("ldmatrix.sync.aligned.m8n8.x4.shared.b16 {%0,%1,%2,%3}, [%4];"
                 : "=r"(r0), "=r"(r1), "=r"(r2), "=r"(r3) : "r"(a));
}
__device__ __forceinline__ void ldmx2(uint32_t& r0, uint32_t& r1, uint32_t a) {
    asm volatile("ldmatrix.sync.aligned.m8n8.x2.shared.b16 {%0,%1}, [%2];"
                 : "=r"(r0), "=r"(r1) : "r"(a));
}
__device__ __forceinline__ void ldmx2t(uint32_t& r0, uint32_t& r1, uint32_t a) {
    asm volatile("ldmatrix.sync.aligned.m8n8.x2.trans.shared.b16 {%0,%1}, [%2];"
                 : "=r"(r0), "=r"(r1) : "r"(a));
}
__device__ __forceinline__ void mma_bf16(float& c0, float& c1, float& c2, float& c3,
                                         const uint32_t a[4], uint32_t b0, uint32_t b1) {
    asm volatile("mma.sync.aligned.m16n8k16.row.col.f32.bf16.bf16.f32 "
                 "{%0,%1,%2,%3}, {%4,%5,%6,%7}, {%8,%9}, {%0,%1,%2,%3};"
                 : "+f"(c0), "+f"(c1), "+f"(c2), "+f"(c3)
                 : "r"(a[0]), "r"(a[1]), "r"(a[2]), "r"(a[3]), "r"(b0), "r"(b1));
}
__device__ __forceinline__ void cp16(uint32_t dst, const void* src) {
    asm volatile("cp.async.cg.shared.global [%0], [%1], 16;" :: "r"(dst), "l"(src));
}
__device__ __forceinline__ void cp_commit() { asm volatile("cp.async.commit_group;"); }
__device__ __forceinline__ void cp_wait1()  { asm volatile("cp.async.wait_group 1;"); }
__device__ __forceinline__ void cp_wait0()  { asm volatile("cp.async.wait_group 0;"); }

// ---------------------------------------------------------------------------
// Kernel 0: weight conversion fp32 -> bf16 hi (+lo residual for V path)
// ---------------------------------------------------------------------------
struct PrepSrc { const float* w[6]; };

__global__ void prep_kernel(PrepSrc S)
{
    int e = blockIdx.y;
    const float* src = S.w[e];
    __nv_bfloat16* hi; __nv_bfloat16* lo = nullptr; int n;
    switch (e) {
        case 0: hi = g_w1h[0]; n = 64*HIDW; break;
        case 1: hi = g_w1h[1]; n = 64*HIDW; break;
        case 2: hi = g_w1h[2]; lo = g_w1l; n = 64*HIDW; break;
        case 3: hi = g_w2h[0]; n = HIDW*NOUT; break;
        case 4: hi = g_w2h[1]; n = HIDW*NOUT; break;
        default: hi = g_w2h[2]; lo = g_w2l; n = HIDW*NOUT; break;
    }
    int i = blockIdx.x * blockDim.x + threadIdx.x;
    if (i < n) {
        float w = src[i];
        __nv_bfloat16 h = __float2bfloat16(w);
        hi[i] = h;
        if (lo) lo[i] = __float2bfloat16(w - __bfloat162float(h));
    }
}

// ---------------------------------------------------------------------------
// Kernel 1 (P1): H = relu(X @ W1 + b1), bf16 out. CTA = 128 rows, 8 warps.
// V (p==2) runs split hi+lo passes over W1.
// ---------------------------------------------------------------------------
struct P1Args { const float* x[3]; const float* b1[3]; };

#define P1_SMEM (128*72*2 + 2*64*264*2)

__global__ void __launch_bounds__(256) p1_kernel(P1Args A)
{
    extern __shared__ char sm[];
    __nv_bfloat16* Xs  = reinterpret_cast<__nv_bfloat16*>(sm);            // [128][72]
    __nv_bfloat16* W1s = reinterpret_cast<__nv_bfloat16*>(sm + 128*72*2); // [2][64][264]

    int p = blockIdx.y;
    const float* x   = A.x[p];
    const float* b1p = A.b1[p];
    int tid = threadIdx.x, w = tid >> 5, lane = tid & 31;
    int r0 = blockIdx.x * 128;

    // X [128][64] fp32 -> bf16 smem
    {
        int r = tid >> 1, c0 = (tid & 1) * 32;
        const float4* src = reinterpret_cast<const float4*>(&x[(size_t)(r0 + r)*64 + c0]);
        __nv_bfloat162 tmp[16];
        #pragma unroll
        for (int i = 0; i < 8; i++) {
            float4 v = src[i];
            tmp[2*i]   = __floats2bfloat162_rn(v.x, v.y);
            tmp[2*i+1] = __floats2bfloat162_rn(v.z, v.w);
        }
        uint4* dst = reinterpret_cast<uint4*>(&Xs[r*72 + c0]);
        const uint4* ts = reinterpret_cast<const uint4*>(tmp);
        dst[0] = ts[0]; dst[1] = ts[1]; dst[2] = ts[2]; dst[3] = ts[3];
    }
    // W1 hi (and lo for V) bf16 -> smem [64][264]
    {
        int nsrc = (p == 2) ? 2 : 1;
        for (int s = 0; s < nsrc; s++) {
            const __nv_bfloat16* g = (s == 0) ? g_w1h[p] : g_w1l;
            #pragma unroll
            for (int j = 0; j < 8; j++) {
                int i = tid + j*256;           // uint4 index over 2048
                int row = i >> 5, c8 = i & 31;
                *reinterpret_cast<uint4*>(&W1s[s*64*264 + row*264 + c8*8]) =
                    *reinterpret_cast<const uint4*>(&g[row*HIDW + c8*8]);
            }
        }
    }
    __syncthreads();

    int l7 = lane & 7, lg = (lane >> 3) & 1, lh = lane >> 4;
    uint32_t af[4][4];
    #pragma unroll
    for (int kc = 0; kc < 4; kc++)
        ldmx4(af[kc][0], af[kc][1], af[kc][2], af[kc][3],
              smem_u32(&Xs[(w*16 + l7 + lg*8)*72 + kc*16 + lh*8]));

    int nsrc = (p == 2) ? 2 : 1;
    int r = lane >> 2, c = (lane & 3)*2;

    #pragma unroll 1
    for (int half = 0; half < 2; half++) {
        float acc[16][4];
        #pragma unroll
        for (int nf = 0; nf < 16; nf++)
            #pragma unroll
            for (int i = 0; i < 4; i++) acc[nf][i] = 0.f;

        #pragma unroll 1
        for (int s = 0; s < nsrc; s++) {
            const __nv_bfloat16* Wb = W1s + s*64*264;
            #pragma unroll
            for (int nf = 0; nf < 16; nf++) {
                #pragma unroll
                for (int kc = 0; kc < 4; kc++) {
                    uint32_t b0, b1;
                    ldmx2t(b0, b1, smem_u32(&Wb[(kc*16 + lg*8 + l7)*264 + half*128 + nf*8]));
                    mma_bf16(acc[nf][0], acc[nf][1], acc[nf][2], acc[nf][3], af[kc], b0, b1);
                }
            }
        }
        // bias + relu + bf16 store
        #pragma unroll
        for (int nf = 0; nf < 16; nf++) {
            int col = half*128 + nf*8 + c;
            float2 bb = *reinterpret_cast<const float2*>(&b1p[col]);
            float v0 = fmaxf(acc[nf][0] + bb.x, 0.f);
            float v1 = fmaxf(acc[nf][1] + bb.y, 0.f);
            float v2 = fmaxf(acc[nf][2] + bb.x, 0.f);
            float v3 = fmaxf(acc[nf][3] + bb.y, 0.f);
            size_t base = (size_t)(r0 + w*16 + r)*HIDW + col;
            *reinterpret_cast<uint32_t*>(&g_hid[p][base])            = pkbf(v0, v1);
            *reinterpret_cast<uint32_t*>(&g_hid[p][base + 8*HIDW])   = pkbf(v2, v3);
        }
    }
}

// ---------------------------------------------------------------------------
// Kernel 2 (P2): Y = H @ W2 + b2 (scale), bf16 out to g_qkv.
// CTA tile 128M x 256N, 16 warps (warp tile 32x64), cp.async double-buffered
// B chunks (32k x 256n), A resident in smem. V (p==2): 16 chunks (hi then lo).
// ---------------------------------------------------------------------------
struct P2Args { const float* b2[3]; float scale[3]; };

#define P2_AS 264
#define P2_SMEM (128*P2_AS*2 + 2*32*P2_AS*2)

__global__ void __launch_bounds__(512) p2_kernel(P2Args A2)
{
    extern __shared__ char sm[];
    __nv_bfloat16* As = reinterpret_cast<__nv_bfloat16*>(sm);               // [128][264]
    __nv_bfloat16* Bs = reinterpret_cast<__nv_bfloat16*>(sm + 128*P2_AS*2); // [2][32][264]

    int p = blockIdx.z, nh = blockIdx.y;
    int r0 = blockIdx.x * 128;
    int tid = threadIdx.x, w = tid >> 5, lane = tid & 31;
    int wm = w & 3, wn = w >> 2;
    int l7 = lane & 7, lg = (lane >> 3) & 1, lh = lane >> 4;

    // issue A (whole 128x256 tile)
    {
        #pragma unroll
        for (int j = 0; j < 8; j++) {
            int i = tid + j*512;
            int row = i >> 5, c8 = i & 31;
            cp16(smem_u32(&As[row*P2_AS + c8*8]),
                 &g_hid[p][(size_t)(r0 + row)*HIDW + c8*8]);
        }
        cp_commit();
    }

    auto issue_b = [&](int kk) {
        const __nv_bfloat16* w2p = (kk < 8) ? g_w2h[p] : g_w2l;
        int k0 = (kk & 7) * 32;
        int buf = kk & 1;
        #pragma unroll
        for (int j = 0; j < 2; j++) {
            int i = tid + j*512;
            int row = i >> 5, c8 = i & 31;
            cp16(smem_u32(&Bs[buf*32*P2_AS + row*P2_AS + c8*8]),
                 &w2p[(size_t)(k0 + row)*NOUT + nh*256 + c8*8]);
        }
        cp_commit();
    };

    issue_b(0);

    float acc[2][8][4];
    #pragma unroll
    for (int m = 0; m < 2; m++)
        #pragma unroll
        for (int nf = 0; nf < 8; nf++)
            #pragma unroll
            for (int i = 0; i < 4; i++) acc[m][nf][i] = 0.f;

    int NC = (p == 2) ? 16 : 8;
    #pragma unroll 1
    for (int kk = 0; kk < NC; kk++) {
        if (kk + 1 < NC) { issue_b(kk + 1); cp_wait1(); }
        else             { cp_wait0(); }
        __syncthreads();

        int buf = kk & 1;
        uint32_t af[2][2][4];
        #pragma unroll
        for (int m = 0; m < 2; m++)
            #pragma unroll
            for (int kc = 0; kc < 2; kc++)
                ldmx4(af[m][kc][0], af[m][kc][1], af[m][kc][2], af[m][kc][3],
                      smem_u32(&As[(wm*32 + m*16 + l7 + lg*8)*P2_AS + (kk & 7)*32 + kc*16 + lh*8]));

        #pragma unroll
        for (int nf = 0; nf < 8; nf++) {
            #pragma unroll
            for (int kc = 0; kc < 2; kc++) {
                uint32_t b0, b1;
                ldmx2t(b0, b1, smem_u32(&Bs[buf*32*P2_AS + (kc*16 + lg*8 + l7)*P2_AS + wn*64 + nf*8]));
                mma_bf16(acc[0][nf][0], acc[0][nf][1], acc[0][nf][2], acc[0][nf][3], af[0][kc], b0, b1);
                mma_bf16(acc[1][nf][0], acc[1][nf][1], acc[1][nf][2], acc[1][nf][3], af[1][kc], b0, b1);
            }
        }
        __syncthreads();
    }

    // epilogue: bias + scale -> bf16 g_qkv
    const float* b2p = A2.b2[p];
    float scale = A2.scale[p];
    int r = lane >> 2, c = (lane & 3)*2;
    #pragma unroll
    for (int m = 0; m < 2; m++) {
        #pragma unroll
        for (int nf = 0; nf < 8; nf++) {
            int row = r0 + wm*32 + m*16 + r;
            int col = nh*256 + wn*64 + nf*8 + c;
            float2 bb = *reinterpret_cast<const float2*>(&b2p[col]);
            float v0 = (acc[m][nf][0] + bb.x) * scale;
            float v1 = (acc[m][nf][1] + bb.y) * scale;
            float v2 = (acc[m][nf][2] + bb.x) * scale;
            float v3 = (acc[m][nf][3] + bb.y) * scale;
            *reinterpret_cast<uint32_t*>(&g_qkv[p][(size_t)row*NOUT + col])       = pkbf(v0, v1);
            *reinterpret_cast<uint32_t*>(&g_qkv[p][(size_t)(row + 8)*NOUT + col]) = pkbf(v2, v3);
        }
    }
}

// ---------------------------------------------------------------------------
// Kernel 3: flash attention. CTA = (b,h,128 t-rows), 8 warps x 16 rows,
// cp.async double-buffered K/V (s-tiles of 64). K/V L2 traffic halved vs
// the 64-row variant; per-warp inner loop identical.
// ---------------------------------------------------------------------------
#define ATT_SMEM (128*72*2 + 4*64*72*2)

__global__ void __launch_bounds__(256, 2) attn_kernel(const float* __restrict__ mask)
{
    extern __shared__ char smc[];
    __nv_bfloat16* Qs = reinterpret_cast<__nv_bfloat16*>(smc);               // [128][72]
    __nv_bfloat16* Ks = reinterpret_cast<__nv_bfloat16*>(smc + 128*72*2);    // [2][64][72]
    __nv_bfloat16* Vs = reinterpret_cast<__nv_bfloat16*>(smc + 128*72*2 + 2*64*72*2);

    int tid = threadIdx.x, w = tid >> 5, lane = tid & 31;
    int t0 = blockIdx.x * 128, h = blockIdx.y, b = blockIdx.z;
    const __nv_bfloat16* qg = g_qkv[0];
    const __nv_bfloat16* kg = g_qkv[1];
    const __nv_bfloat16* vg = g_qkv[2];

    // load Q tile [128][64]
    {
        int r = tid >> 1, part = tid & 1;
        const uint4* src = reinterpret_cast<const uint4*>(
            &qg[((size_t)(t0 + r)*B_DIM + b)*NOUT + h*64 + part*32]);
        uint4* dst = reinterpret_cast<uint4*>(&Qs[r*72 + part*32]);
        dst[0] = src[0]; dst[1] = src[1]; dst[2] = src[2]; dst[3] = src[3];
    }

    // K/V staging: 256 threads cover 64 rows x 64 cols; each thread 16 cols (32B)
    int lr = tid >> 2, lc = (tid & 3) * 16;
    const __nv_bfloat16* kbase = &kg[((size_t)lr*B_DIM + b)*NOUT + h*64 + lc];
    const __nv_bfloat16* vbase = &vg[((size_t)lr*B_DIM + b)*NOUT + h*64 + lc];
    uint32_t dK0 = smem_u32(&Ks[lr*72 + lc]);
    uint32_t dV0 = smem_u32(&Vs[lr*72 + lc]);
    const uint32_t bufstride = 64*72*2;  // bytes per buffer

    auto issue = [&](int it, int buf) {
        size_t off = (size_t)it * 64 * B_DIM * NOUT;
        const char* sK = reinterpret_cast<const char*>(kbase + off);
        const char* sV = reinterpret_cast<const char*>(vbase + off);
        uint32_t dK = dK0 + buf*bufstride, dV = dV0 + buf*bufstride;
        #pragma unroll
        for (int i = 0; i < 2; i++) {
            cp16(dK + i*16, sK + i*16);
            cp16(dV + i*16, sV + i*16);
        }
        cp_commit();
    };

    issue(0, 0);
    __syncthreads();   // Qs ready

    uint32_t qf[4][4];
    {
        int g2 = lane >> 3;
        #pragma unroll
        for (int kc = 0; kc < 4; kc++) {
            uint32_t a = smem_u32(&Qs[(w*16 + (lane & 7) + (g2 & 1)*8)*72 + kc*16 + (g2 >> 1)*8]);
            ldmx4(qf[kc][0], qf[kc][1], qf[kc][2], qf[kc][3], a);
        }
    }

    float accO[8][4];
    #pragma unroll
    for (int d = 0; d < 8; d++)
        #pragma unroll
        for (int i = 0; i < 4; i++) accO[d][i] = 0.f;

    float lsum_lo = 0.f, lsum_hi = 0.f;
    const float* mbase = mask + ((size_t)b*T_DIM + (t0 + w*16 + (lane >> 2)))*S_DIM + (lane & 3)*2;
    int lg = (lane >> 3) & 1, l7 = lane & 7;

    #pragma unroll 1
    for (int it = 0; it < S_DIM/64; it++) {
        if (it + 1 < S_DIM/64) { issue(it + 1, (it + 1) & 1); cp_wait1(); }
        else                   { cp_wait0(); }
        __syncthreads();
        const __nv_bfloat16* Kb = Ks + (it & 1)*64*72;
        const __nv_bfloat16* Vb = Vs + (it & 1)*64*72;
        int s0 = it * 64;

        // S = Q @ K^T, +mask, exp -> P fragments (registers)
        uint32_t pa[4][4];
        #pragma unroll
        for (int n = 0; n < 8; n++) {
            float c0 = 0.f, c1 = 0.f, c2 = 0.f, c3 = 0.f;
            #pragma unroll
            for (int kc = 0; kc < 4; kc++) {
                uint32_t b0, b1;
                ldmx2(b0, b1, smem_u32(&Kb[(n*8 + l7)*72 + kc*16 + lg*8]));
                mma_bf16(c0, c1, c2, c3, qf[kc], b0, b1);
            }
            const float* mp = mbase + s0 + n*8;
            float2 m0 = *reinterpret_cast<const float2*>(mp);
            float2 m1 = *reinterpret_cast<const float2*>(mp + 8*(size_t)S_DIM);
            float e0 = __expf(c0 + m0.x), e1 = __expf(c1 + m0.y);
            float e2 = __expf(c2 + m1.x), e3 = __expf(c3 + m1.y);
            lsum_lo += e0 + e1;
            lsum_hi += e2 + e3;
            pa[n >> 1][(n & 1)*2 + 0] = pkbf(e0, e1);
            pa[n >> 1][(n & 1)*2 + 1] = pkbf(e2, e3);
        }

        // O += P @ V
        #pragma unroll
        for (int d = 0; d < 8; d++) {
            #pragma unroll
            for (int kc = 0; kc < 4; kc++) {
                uint32_t b0, b1;
                ldmx2t(b0, b1, smem_u32(&Vb[(kc*16 + lg*8 + l7)*72 + d*8]));
                mma_bf16(accO[d][0], accO[d][1], accO[d][2], accO[d][3], pa[kc], b0, b1);
            }
        }
        __syncthreads();
    }

    // reduce row sums across quads
    lsum_lo += __shfl_xor_sync(0xffffffffu, lsum_lo, 1);
    lsum_lo += __shfl_xor_sync(0xffffffffu, lsum_lo, 2);
    lsum_hi += __shfl_xor_sync(0xffffffffu, lsum_hi, 1);
    lsum_hi += __shfl_xor_sync(0xffffffffu, lsum_hi, 2);
    float inv_lo = 1.f / lsum_lo, inv_hi = 1.f / lsum_hi;

    int row = t0 + w*16 + (lane >> 2);
    float* o_lo = &g_ctx[((size_t)row*B_DIM + b)*NOUT + h*64 + (lane & 3)*2];
    float* o_hi = o_lo + (size_t)8*B_DIM*NOUT;
    #pragma unroll
    for (int d = 0; d < 8; d++) {
        float2 vlo = { accO[d][0]*inv_lo, accO[d][1]*inv_lo };
        float2 vhi = { accO[d][2]*inv_hi, accO[d][3]*inv_hi };
        *reinterpret_cast<float2*>(o_lo + d*8) = vlo;
        *reinterpret_cast<float2*>(o_hi + d*8) = vhi;
    }
}

// ---------------------------------------------------------------------------
// Kernel 4: out = ctx @ Wo + bo  (fp32, unchanged)
// ---------------------------------------------------------------------------
__global__ void outproj_kernel(const float* __restrict__ Wo, const float* __restrict__ bo,
                               float* __restrict__ out)
{
    __shared__ float ctxT[64][68];
    int tid = threadIdx.x;
    int r0  = blockIdx.x * 64;
    int j   = tid & 63, rg = tid >> 6;
    float acc[16];
    #pragma unroll
    for (int i = 0; i < 16; i++) acc[i] = 0.f;

    #pragma unroll 1
    for (int kt = 0; kt < 8; kt++) {
        if (kt) __syncthreads();
        {
            int r = tid >> 2, q = tid & 3;
            #pragma unroll
            for (int i = 0; i < 4; i++) {
                int k = q*16 + i*4;
                float4 v4 = *reinterpret_cast<const float4*>(
                    &g_ctx[(size_t)(r0 + r)*NOUT + kt*64 + k]);
                ctxT[k+0][r] = v4.x;
                ctxT[k+1][r] = v4.y;
                ctxT[k+2][r] = v4.z;
                ctxT[k+3][r] = v4.w;
            }
        }
        __syncthreads();
        #pragma unroll 4
        for (int k = 0; k < 64; k++) {
            float wv = Wo[(size_t)(kt*64 + k)*64 + j];
            #pragma unroll
            for (int rr = 0; rr < 16; rr += 4) {
                float4 c4 = *reinterpret_cast<const float4*>(&ctxT[k][rg*16 + rr]);
                acc[rr+0] += wv * c4.x;
                acc[rr+1] += wv * c4.y;
                acc[rr+2] += wv * c4.z;
                acc[rr+3] += wv * c4.w;
            }
        }
    }
    float bj = bo[j];
    #pragma unroll
    for (int rr = 0; rr < 16; rr++)
        out[(size_t)(r0 + rg*16 + rr)*64 + j] = acc[rr] + bj;
}

// ---------------------------------------------------------------------------
extern "C" void kernel_launch(void* const* d_in, const int* in_sizes, int n_in,
                              void* d_out, int out_size)
{
    const float* query = (const float*)d_in[0];
    const float* key   = (const float*)d_in[1];
    const float* value = (const float*)d_in[2];
    const float* mask  = (const float*)d_in[3];
    const float* Wq1 = (const float*)d_in[4];  const float* bq1 = (const float*)d_in[5];
    const float* Wq2 = (const float*)d_in[6];  const float* bq2 = (const float*)d_in[7];
    const float* Wk1 = (const float*)d_in[8];  const float* bk1 = (const float*)d_in[9];
    const float* Wk2 = (const float*)d_in[10]; const float* bk2 = (const float*)d_in[11];
    const float* Wv1 = (const float*)d_in[12]; const float* bv1 = (const float*)d_in[13];
    const float* Wv2 = (const float*)d_in[14]; const float* bv2 = (const float*)d_in[15];
    const float* Wo  = (const float*)d_in[16];
    const float* bo  = (const float*)d_in[17];
    float* out = (float*)d_out;

    PrepSrc S;
    S.w[0] = Wq1; S.w[1] = Wk1; S.w[2] = Wv1;
    S.w[3] = Wq2; S.w[4] = Wk2; S.w[5] = Wv2;

    P1Args A1;
    A1.x[0] = query; A1.x[1] = key; A1.x[2] = value;
    A1.b1[0] = bq1;  A1.b1[1] = bk1; A1.b1[2] = bv1;

    P2Args A2;
    A2.b2[0] = bq2; A2.b2[1] = bk2; A2.b2[2] = bv2;
    A2.scale[0] = 0.125f; A2.scale[1] = 1.0f; A2.scale[2] = 1.0f;

    cudaFuncSetAttribute(p1_kernel, cudaFuncAttributeMaxDynamicSharedMemorySize, P1_SMEM);
    cudaFuncSetAttribute(p2_kernel, cudaFuncAttributeMaxDynamicSharedMemorySize, P2_SMEM);
    cudaFuncSetAttribute(attn_kernel, cudaFuncAttributeMaxDynamicSharedMemorySize, ATT_SMEM);

    prep_kernel<<<dim3(512, 6), 256>>>(S);
    p1_kernel<<<dim3(64, 3), 256, P1_SMEM>>>(A1);
    p2_kernel<<<dim3(64, 2, 3), 512, P2_SMEM>>>(A2);
    attn_kernel<<<dim3(16, 8, 4), 256, ATT_SMEM>>>(mask);
    outproj_kernel<<<128, 256>>>(Wo, bo, out);
}

// round 10
// speedup vs baseline: 4.8741x; 1.0356x over previous
#include <cuda_runtime.h>
#include <cuda_bf16.h>
#include <cstdint>

#define T_DIM 2048
#define S_DIM 2048
#define B_DIM 4
#define H_DIM 8
#define NOUT 512
#define HIDW 256
#define NROWS (T_DIM*B_DIM)

// scratch (device globals; no allocation allowed)
__device__ __align__(128) __nv_bfloat16 g_qkv[3][(size_t)NROWS*NOUT];
__device__ __align__(128) float g_ctx[(size_t)NROWS*NOUT];
__device__ __align__(128) __nv_bfloat16 g_hid[3][(size_t)NROWS*HIDW];
__device__ __align__(128) __nv_bfloat16 g_w1h[3][64*HIDW];
__device__ __align__(128) __nv_bfloat16 g_w1l[64*HIDW];
__device__ __align__(128) __nv_bfloat16 g_w2h[3][HIDW*NOUT];
__device__ __align__(128) __nv_bfloat16 g_w2l[HIDW*NOUT];

// ---------------------------------------------------------------------------
// helpers
// ---------------------------------------------------------------------------
__device__ __forceinline__ uint32_t smem_u32(const void* p) {
    return (uint32_t)__cvta_generic_to_shared(p);
}
__device__ __forceinline__ uint32_t pkbf(float a, float b) {
    __nv_bfloat162 t = __floats2bfloat162_rn(a, b);
    return *reinterpret_cast<uint32_t*>(&t);
}
__device__ __forceinline__ void ldmx4(uint32_t& r0, uint32_t& r1, uint32_t& r2, uint32_t& r3, uint32_t a) {
    asm volatile("ldmatrix.sync.aligned.m8n8.x4.shared.b16 {%0,%1,%2,%3}, [%4];"
                 : "=r"(r0), "=r"(r1), "=r"(r2), "=r"(r3) : "r"(a));
}
__device__ __forceinline__ void ldmx4t(uint32_t& r0, uint32_t& r1, uint32_t& r2, uint32_t& r3, uint32_t a) {
    asm volatile("ldmatrix.sync.aligned.m8n8.x4.trans.shared.b16 {%0,%1,%2,%3}, [%4];"
                 : "=r"(r0), "=r"(r1), "=r"(r2), "=r"(r3) : "r"(a));
}
__device__ __forceinline__ void ldmx2t(uint32_t& r0, uint32_t& r1, uint32_t a) {
    asm volatile("ldmatrix.sync.aligned.m8n8.x2.trans.shared.b16 {%0,%1}, [%2];"
                 : "=r"(r0), "=r"(r1) : "r"(a));
}
__device__ __forceinline__ void mma_bf16(float& c0, float& c1, float& c2, float& c3,
                                         const uint32_t a[4], uint32_t b0, uint32_t b1) {
    asm volatile("mma.sync.aligned.m16n8k16.row.col.f32.bf16.bf16.f32 "
                 "{%0,%1,%2,%3}, {%4,%5,%6,%7}, {%8,%9}, {%0,%1,%2,%3};"
                 : "+f"(c0), "+f"(c1), "+f"(c2), "+f"(c3)
                 : "r"(a[0]), "r"(a[1]), "r"(a[2]), "r"(a[3]), "r"(b0), "r"(b1));
}
__device__ __forceinline__ void cp16(uint32_t dst, const void* src) {
    asm volatile("cp.async.cg.shared.global [%0], [%1], 16;" :: "r"(dst), "l"(src));
}
__device__ __forceinline__ void cp_commit() { asm volatile("cp.async.commit_group;"); }
__device__ __forceinline__ void cp_wait1()  { asm volatile("cp.async.wait_group 1;"); }
__device__ __forceinline__ void cp_wait0()  { asm volatile("cp.async.wait_group 0;"); }

// ---------------------------------------------------------------------------
// Kernel 0: weight conversion fp32 -> bf16 hi (+lo residual for V path)
// ---------------------------------------------------------------------------
struct PrepSrc { const float* w[6]; };

__global__ void prep_kernel(PrepSrc S)
{
    int e = blockIdx.y;
    const float* src = S.w[e];
    __nv_bfloat16* hi; __nv_bfloat16* lo = nullptr; int n;
    switch (e) {
        case 0: hi = g_w1h[0]; n = 64*HIDW; break;
        case 1: hi = g_w1h[1]; n = 64*HIDW; break;
        case 2: hi = g_w1h[2]; lo = g_w1l; n = 64*HIDW; break;
        case 3: hi = g_w2h[0]; n = HIDW*NOUT; break;
        case 4: hi = g_w2h[1]; n = HIDW*NOUT; break;
        default: hi = g_w2h[2]; lo = g_w2l; n = HIDW*NOUT; break;
    }
    int i = blockIdx.x * blockDim.x + threadIdx.x;
    if (i < n) {
        float w = src[i];
        __nv_bfloat16 h = __float2bfloat16(w);
        hi[i] = h;
        if (lo) lo[i] = __float2bfloat16(w - __bfloat162float(h));
    }
}

// ---------------------------------------------------------------------------
// Kernel 1 (P1): H = relu(X @ W1 + b1), bf16 out. CTA = 128 rows, 8 warps.
// V (p==2) runs split hi+lo passes over W1.  (unchanged from R3)
// ---------------------------------------------------------------------------
struct P1Args { const float* x[3]; const float* b1[3]; };

#define P1_SMEM (128*72*2 + 2*64*264*2)

__global__ void __launch_bounds__(256) p1_kernel(P1Args A)
{
    extern __shared__ char sm[];
    __nv_bfloat16* Xs  = reinterpret_cast<__nv_bfloat16*>(sm);            // [128][72]
    __nv_bfloat16* W1s = reinterpret_cast<__nv_bfloat16*>(sm + 128*72*2); // [2][64][264]

    int p = blockIdx.y;
    const float* x   = A.x[p];
    const float* b1p = A.b1[p];
    int tid = threadIdx.x, w = tid >> 5, lane = tid & 31;
    int r0 = blockIdx.x * 128;

    {
        int r = tid >> 1, c0 = (tid & 1) * 32;
        const float4* src = reinterpret_cast<const float4*>(&x[(size_t)(r0 + r)*64 + c0]);
        __nv_bfloat162 tmp[16];
        #pragma unroll
        for (int i = 0; i < 8; i++) {
            float4 v = src[i];
            tmp[2*i]   = __floats2bfloat162_rn(v.x, v.y);
            tmp[2*i+1] = __floats2bfloat162_rn(v.z, v.w);
        }
        uint4* dst = reinterpret_cast<uint4*>(&Xs[r*72 + c0]);
        const uint4* ts = reinterpret_cast<const uint4*>(tmp);
        dst[0] = ts[0]; dst[1] = ts[1]; dst[2] = ts[2]; dst[3] = ts[3];
    }
    {
        int nsrc = (p == 2) ? 2 : 1;
        for (int s = 0; s < nsrc; s++) {
            const __nv_bfloat16* g = (s == 0) ? g_w1h[p] : g_w1l;
            #pragma unroll
            for (int j = 0; j < 8; j++) {
                int i = tid + j*256;
                int row = i >> 5, c8 = i & 31;
                *reinterpret_cast<uint4*>(&W1s[s*64*264 + row*264 + c8*8]) =
                    *reinterpret_cast<const uint4*>(&g[row*HIDW + c8*8]);
            }
        }
    }
    __syncthreads();

    int l7 = lane & 7, lg = (lane >> 3) & 1, lh = lane >> 4;
    uint32_t af[4][4];
    #pragma unroll
    for (int kc = 0; kc < 4; kc++)
        ldmx4(af[kc][0], af[kc][1], af[kc][2], af[kc][3],
              smem_u32(&Xs[(w*16 + l7 + lg*8)*72 + kc*16 + lh*8]));

    int nsrc = (p == 2) ? 2 : 1;
    int r = lane >> 2, c = (lane & 3)*2;

    #pragma unroll 1
    for (int half = 0; half < 2; half++) {
        float acc[16][4];
        #pragma unroll
        for (int nf = 0; nf < 16; nf++)
            #pragma unroll
            for (int i = 0; i < 4; i++) acc[nf][i] = 0.f;

        #pragma unroll 1
        for (int s = 0; s < nsrc; s++) {
            const __nv_bfloat16* Wb = W1s + s*64*264;
            #pragma unroll
            for (int nf = 0; nf < 16; nf++) {
                #pragma unroll
                for (int kc = 0; kc < 4; kc++) {
                    uint32_t b0, b1;
                    ldmx2t(b0, b1, smem_u32(&Wb[(kc*16 + lg*8 + l7)*264 + half*128 + nf*8]));
                    mma_bf16(acc[nf][0], acc[nf][1], acc[nf][2], acc[nf][3], af[kc], b0, b1);
                }
            }
        }
        #pragma unroll
        for (int nf = 0; nf < 16; nf++) {
            int col = half*128 + nf*8 + c;
            float2 bb = *reinterpret_cast<const float2*>(&b1p[col]);
            float v0 = fmaxf(acc[nf][0] + bb.x, 0.f);
            float v1 = fmaxf(acc[nf][1] + bb.y, 0.f);
            float v2 = fmaxf(acc[nf][2] + bb.x, 0.f);
            float v3 = fmaxf(acc[nf][3] + bb.y, 0.f);
            size_t base = (size_t)(r0 + w*16 + r)*HIDW + col;
            *reinterpret_cast<uint32_t*>(&g_hid[p][base])            = pkbf(v0, v1);
            *reinterpret_cast<uint32_t*>(&g_hid[p][base + 8*HIDW])   = pkbf(v2, v3);
        }
    }
}

// ---------------------------------------------------------------------------
// Kernel 2 (P2): Y = H @ W2 + b2 (scale), bf16 out to g_qkv. (unchanged)
// ---------------------------------------------------------------------------
struct P2Args { const float* b2[3]; float scale[3]; };

#define P2_AS 264
#define P2_SMEM (128*P2_AS*2 + 2*32*P2_AS*2)

__global__ void __launch_bounds__(512) p2_kernel(P2Args A2)
{
    extern __shared__ char sm[];
    __nv_bfloat16* As = reinterpret_cast<__nv_bfloat16*>(sm);               // [128][264]
    __nv_bfloat16* Bs = reinterpret_cast<__nv_bfloat16*>(sm + 128*P2_AS*2); // [2][32][264]

    int p = blockIdx.z, nh = blockIdx.y;
    int r0 = blockIdx.x * 128;
    int tid = threadIdx.x, w = tid >> 5, lane = tid & 31;
    int wm = w & 3, wn = w >> 2;
    int l7 = lane & 7, lg = (lane >> 3) & 1, lh = lane >> 4;

    {
        #pragma unroll
        for (int j = 0; j < 8; j++) {
            int i = tid + j*512;
            int row = i >> 5, c8 = i & 31;
            cp16(smem_u32(&As[row*P2_AS + c8*8]),
                 &g_hid[p][(size_t)(r0 + row)*HIDW + c8*8]);
        }
        cp_commit();
    }

    auto issue_b = [&](int kk) {
        const __nv_bfloat16* w2p = (kk < 8) ? g_w2h[p] : g_w2l;
        int k0 = (kk & 7) * 32;
        int buf = kk & 1;
        #pragma unroll
        for (int j = 0; j < 2; j++) {
            int i = tid + j*512;
            int row = i >> 5, c8 = i & 31;
            cp16(smem_u32(&Bs[buf*32*P2_AS + row*P2_AS + c8*8]),
                 &w2p[(size_t)(k0 + row)*NOUT + nh*256 + c8*8]);
        }
        cp_commit();
    };

    issue_b(0);

    float acc[2][8][4];
    #pragma unroll
    for (int m = 0; m < 2; m++)
        #pragma unroll
        for (int nf = 0; nf < 8; nf++)
            #pragma unroll
            for (int i = 0; i < 4; i++) acc[m][nf][i] = 0.f;

    int NC = (p == 2) ? 16 : 8;
    #pragma unroll 1
    for (int kk = 0; kk < NC; kk++) {
        if (kk + 1 < NC) { issue_b(kk + 1); cp_wait1(); }
        else             { cp_wait0(); }
        __syncthreads();

        int buf = kk & 1;
        uint32_t af[2][2][4];
        #pragma unroll
        for (int m = 0; m < 2; m++)
            #pragma unroll
            for (int kc = 0; kc < 2; kc++)
                ldmx4(af[m][kc][0], af[m][kc][1], af[m][kc][2], af[m][kc][3],
                      smem_u32(&As[(wm*32 + m*16 + l7 + lg*8)*P2_AS + (kk & 7)*32 + kc*16 + lh*8]));

        #pragma unroll
        for (int nf = 0; nf < 8; nf++) {
            #pragma unroll
            for (int kc = 0; kc < 2; kc++) {
                uint32_t b0, b1;
                ldmx2t(b0, b1, smem_u32(&Bs[buf*32*P2_AS + (kc*16 + lg*8 + l7)*P2_AS + wn*64 + nf*8]));
                mma_bf16(acc[0][nf][0], acc[0][nf][1], acc[0][nf][2], acc[0][nf][3], af[0][kc], b0, b1);
                mma_bf16(acc[1][nf][0], acc[1][nf][1], acc[1][nf][2], acc[1][nf][3], af[1][kc], b0, b1);
            }
        }
        __syncthreads();
    }

    const float* b2p = A2.b2[p];
    float scale = A2.scale[p];
    int r = lane >> 2, c = (lane & 3)*2;
    #pragma unroll
    for (int m = 0; m < 2; m++) {
        #pragma unroll
        for (int nf = 0; nf < 8; nf++) {
            int row = r0 + wm*32 + m*16 + r;
            int col = nh*256 + wn*64 + nf*8 + c;
            float2 bb = *reinterpret_cast<const float2*>(&b2p[col]);
            float v0 = (acc[m][nf][0] + bb.x) * scale;
            float v1 = (acc[m][nf][1] + bb.y) * scale;
            float v2 = (acc[m][nf][2] + bb.x) * scale;
            float v3 = (acc[m][nf][3] + bb.y) * scale;
            *reinterpret_cast<uint32_t*>(&g_qkv[p][(size_t)row*NOUT + col])       = pkbf(v0, v1);
            *reinterpret_cast<uint32_t*>(&g_qkv[p][(size_t)(row + 8)*NOUT + col]) = pkbf(v2, v3);
        }
    }
}

// ---------------------------------------------------------------------------
// Kernel 3: flash attention. CTA = (b,h,128 t-rows), 4 warps x 32 rows
// (2 bands of 16). ldmx4 for K/V (n/d pairs packed). cp.async double-buffered
// K/V. Halved smem ldmatrix traffic + halved ldmatrix instruction count vs R6.
// ---------------------------------------------------------------------------
#define ATT_SMEM (128*72*2 + 4*64*72*2)

__global__ void __launch_bounds__(128, 2) attn_kernel(const float* __restrict__ mask)
{
    extern __shared__ char smc[];
    __nv_bfloat16* Qs = reinterpret_cast<__nv_bfloat16*>(smc);                      // [128][72]
    __nv_bfloat16* Ks = reinterpret_cast<__nv_bfloat16*>(smc + 128*72*2);           // [2][64][72]
    __nv_bfloat16* Vs = reinterpret_cast<__nv_bfloat16*>(smc + 128*72*2 + 2*64*72*2);

    int tid = threadIdx.x, w = tid >> 5, lane = tid & 31;
    int t0 = blockIdx.x * 128, h = blockIdx.y, b = blockIdx.z;
    const __nv_bfloat16* qg = g_qkv[0];
    const __nv_bfloat16* kg = g_qkv[1];
    const __nv_bfloat16* vg = g_qkv[2];

    // load Q tile [128][64] (one row per thread)
    {
        const uint4* src = reinterpret_cast<const uint4*>(
            &qg[((size_t)(t0 + tid)*B_DIM + b)*NOUT + h*64]);
        uint4* dst = reinterpret_cast<uint4*>(&Qs[tid*72]);
        #pragma unroll
        for (int i = 0; i < 8; i++) dst[i] = src[i];
    }

    // K/V staging: 128 threads, 2 per row, 32 cols (64B = 4x cp16) each
    int lr = tid >> 1, lpart = tid & 1;
    const __nv_bfloat16* kbase = &kg[((size_t)lr*B_DIM + b)*NOUT + h*64 + lpart*32];
    const __nv_bfloat16* vbase = &vg[((size_t)lr*B_DIM + b)*NOUT + h*64 + lpart*32];
    uint32_t dK0 = smem_u32(&Ks[lr*72 + lpart*32]);
    uint32_t dV0 = smem_u32(&Vs[lr*72 + lpart*32]);
    const uint32_t bufstride = 64*72*2;

    auto issue = [&](int it, int buf) {
        size_t off = (size_t)it * 64 * B_DIM * NOUT;
        const char* sK = reinterpret_cast<const char*>(kbase + off);
        const char* sV = reinterpret_cast<const char*>(vbase + off);
        uint32_t dK = dK0 + buf*bufstride, dV = dV0 + buf*bufstride;
        #pragma unroll
        for (int i = 0; i < 4; i++) {
            cp16(dK + i*16, sK + i*16);
            cp16(dV + i*16, sV + i*16);
        }
        cp_commit();
    };

    issue(0, 0);
    __syncthreads();   // Qs ready

    int l7 = lane & 7;
    int lb3 = (lane >> 3) & 1, lb4 = (lane >> 4) & 1;
    int g2 = lane >> 3;

    // Q fragments: 2 bands x 4 k-chunks (persist whole kernel)
    uint32_t qf[2][4][4];
    #pragma unroll
    for (int band = 0; band < 2; band++)
        #pragma unroll
        for (int kc = 0; kc < 4; kc++)
            ldmx4(qf[band][kc][0], qf[band][kc][1], qf[band][kc][2], qf[band][kc][3],
                  smem_u32(&Qs[(w*32 + band*16 + l7 + (g2 & 1)*8)*72 + kc*16 + (g2 >> 1)*8]));

    float accO[2][8][4];
    #pragma unroll
    for (int band = 0; band < 2; band++)
        #pragma unroll
        for (int d = 0; d < 8; d++)
            #pragma unroll
            for (int i = 0; i < 4; i++) accO[band][d][i] = 0.f;

    float ls[2][2] = {{0.f, 0.f}, {0.f, 0.f}};
    const float* mrow[2];
    #pragma unroll
    for (int band = 0; band < 2; band++)
        mrow[band] = mask + ((size_t)b*T_DIM + (t0 + w*32 + band*16 + (lane >> 2)))*S_DIM + (lane & 3)*2;

    #pragma unroll 1
    for (int it = 0; it < S_DIM/64; it++) {
        if (it + 1 < S_DIM/64) { issue(it + 1, (it + 1) & 1); cp_wait1(); }
        else                   { cp_wait0(); }
        __syncthreads();
        const __nv_bfloat16* Kb = Ks + (it & 1)*64*72;
        const __nv_bfloat16* Vb = Vs + (it & 1)*64*72;
        int s0 = it * 64;

        // S = Q @ K^T per npair (16 s-cols), +mask, exp -> P fragments
        uint32_t pa[2][4][4];
        #pragma unroll
        for (int np = 0; np < 4; np++) {
            float c[2][2][4];
            #pragma unroll
            for (int band = 0; band < 2; band++)
                #pragma unroll
                for (int nb = 0; nb < 2; nb++)
                    #pragma unroll
                    for (int i = 0; i < 4; i++) c[band][nb][i] = 0.f;
            #pragma unroll
            for (int kc = 0; kc < 4; kc++) {
                uint32_t r0, r1, r2, r3;
                ldmx4(r0, r1, r2, r3,
                      smem_u32(&Kb[(np*16 + l7 + lb4*8)*72 + kc*16 + lb3*8]));
                #pragma unroll
                for (int band = 0; band < 2; band++) {
                    mma_bf16(c[band][0][0], c[band][0][1], c[band][0][2], c[band][0][3], qf[band][kc], r0, r1);
                    mma_bf16(c[band][1][0], c[band][1][1], c[band][1][2], c[band][1][3], qf[band][kc], r2, r3);
                }
            }
            #pragma unroll
            for (int band = 0; band < 2; band++) {
                #pragma unroll
                for (int nb = 0; nb < 2; nb++) {
                    const float* mp = mrow[band] + s0 + (np*2 + nb)*8;
                    float2 m0 = *reinterpret_cast<const float2*>(mp);
                    float2 m1 = *reinterpret_cast<const float2*>(mp + 8*(size_t)S_DIM);
                    float e0 = __expf(c[band][nb][0] + m0.x);
                    float e1 = __expf(c[band][nb][1] + m0.y);
                    float e2 = __expf(c[band][nb][2] + m1.x);
                    float e3 = __expf(c[band][nb][3] + m1.y);
                    ls[band][0] += e0 + e1;
                    ls[band][1] += e2 + e3;
                    pa[band][np][nb*2 + 0] = pkbf(e0, e1);
                    pa[band][np][nb*2 + 1] = pkbf(e2, e3);
                }
            }
        }

        // O += P @ V per dpair (16 d-cols)
        #pragma unroll
        for (int dp = 0; dp < 4; dp++) {
            #pragma unroll
            for (int kc = 0; kc < 4; kc++) {
                uint32_t r0, r1, r2, r3;
                ldmx4t(r0, r1, r2, r3,
                       smem_u32(&Vb[(kc*16 + l7 + lb3*8)*72 + dp*16 + lb4*8]));
                #pragma unroll
                for (int band = 0; band < 2; band++) {
                    mma_bf16(accO[band][dp*2+0][0], accO[band][dp*2+0][1], accO[band][dp*2+0][2], accO[band][dp*2+0][3], pa[band][kc], r0, r1);
                    mma_bf16(accO[band][dp*2+1][0], accO[band][dp*2+1][1], accO[band][dp*2+1][2], accO[band][dp*2+1][3], pa[band][kc], r2, r3);
                }
            }
        }
        __syncthreads();
    }

    // epilogue per band: reduce row sums across quads, normalize, store
    #pragma unroll
    for (int band = 0; band < 2; band++) {
        float slo = ls[band][0], shi = ls[band][1];
        slo += __shfl_xor_sync(0xffffffffu, slo, 1);
        slo += __shfl_xor_sync(0xffffffffu, slo, 2);
        shi += __shfl_xor_sync(0xffffffffu, shi, 1);
        shi += __shfl_xor_sync(0xffffffffu, shi, 2);
        float inv_lo = 1.f / slo, inv_hi = 1.f / shi;

        int row = t0 + w*32 + band*16 + (lane >> 2);
        float* o_lo = &g_ctx[((size_t)row*B_DIM + b)*NOUT + h*64 + (lane & 3)*2];
        float* o_hi = o_lo + (size_t)8*B_DIM*NOUT;
        #pragma unroll
        for (int d = 0; d < 8; d++) {
            float2 vlo = { accO[band][d][0]*inv_lo, accO[band][d][1]*inv_lo };
            float2 vhi = { accO[band][d][2]*inv_hi, accO[band][d][3]*inv_hi };
            *reinterpret_cast<float2*>(o_lo + d*8) = vlo;
            *reinterpret_cast<float2*>(o_hi + d*8) = vhi;
        }
    }
}

// ---------------------------------------------------------------------------
// Kernel 4: out = ctx @ Wo + bo  (fp32, unchanged)
// ---------------------------------------------------------------------------
__global__ void outproj_kernel(const float* __restrict__ Wo, const float* __restrict__ bo,
                               float* __restrict__ out)
{
    __shared__ float ctxT[64][68];
    int tid = threadIdx.x;
    int r0  = blockIdx.x * 64;
    int j   = tid & 63, rg = tid >> 6;
    float acc[16];
    #pragma unroll
    for (int i = 0; i < 16; i++) acc[i] = 0.f;

    #pragma unroll 1
    for (int kt = 0; kt < 8; kt++) {
        if (kt) __syncthreads();
        {
            int r = tid >> 2, q = tid & 3;
            #pragma unroll
            for (int i = 0; i < 4; i++) {
                int k = q*16 + i*4;
                float4 v4 = *reinterpret_cast<const float4*>(
                    &g_ctx[(size_t)(r0 + r)*NOUT + kt*64 + k]);
                ctxT[k+0][r] = v4.x;
                ctxT[k+1][r] = v4.y;
                ctxT[k+2][r] = v4.z;
                ctxT[k+3][r] = v4.w;
            }
        }
        __syncthreads();
        #pragma unroll 4
        for (int k = 0; k < 64; k++) {
            float wv = Wo[(size_t)(kt*64 + k)*64 + j];
            #pragma unroll
            for (int rr = 0; rr < 16; rr += 4) {
                float4 c4 = *reinterpret_cast<const float4*>(&ctxT[k][rg*16 + rr]);
                acc[rr+0] += wv * c4.x;
                acc[rr+1] += wv * c4.y;
                acc[rr+2] += wv * c4.z;
                acc[rr+3] += wv * c4.w;
            }
        }
    }
    float bj = bo[j];
    #pragma unroll
    for (int rr = 0; rr < 16; rr++)
        out[(size_t)(r0 + rg*16 + rr)*64 + j] = acc[rr] + bj;
}

// ---------------------------------------------------------------------------
extern "C" void kernel_launch(void* const* d_in, const int* in_sizes, int n_in,
                              void* d_out, int out_size)
{
    const float* query = (const float*)d_in[0];
    const float* key   = (const float*)d_in[1];
    const float* value = (const float*)d_in[2];
    const float* mask  = (const float*)d_in[3];
    const float* Wq1 = (const float*)d_in[4];  const float* bq1 = (const float*)d_in[5];
    const float* Wq2 = (const float*)d_in[6];  const float* bq2 = (const float*)d_in[7];
    const float* Wk1 = (const float*)d_in[8];  const float* bk1 = (const float*)d_in[9];
    const float* Wk2 = (const float*)d_in[10]; const float* bk2 = (const float*)d_in[11];
    const float* Wv1 = (const float*)d_in[12]; const float* bv1 = (const float*)d_in[13];
    const float* Wv2 = (const float*)d_in[14]; const float* bv2 = (const float*)d_in[15];
    const float* Wo  = (const float*)d_in[16];
    const float* bo  = (const float*)d_in[17];
    float* out = (float*)d_out;

    PrepSrc S;
    S.w[0] = Wq1; S.w[1] = Wk1; S.w[2] = Wv1;
    S.w[3] = Wq2; S.w[4] = Wk2; S.w[5] = Wv2;

    P1Args A1;
    A1.x[0] = query; A1.x[1] = key; A1.x[2] = value;
    A1.b1[0] = bq1;  A1.b1[1] = bk1; A1.b1[2] = bv1;

    P2Args A2;
    A2.b2[0] = bq2; A2.b2[1] = bk2; A2.b2[2] = bv2;
    A2.scale[0] = 0.125f; A2.scale[1] = 1.0f; A2.scale[2] = 1.0f;

    cudaFuncSetAttribute(p1_kernel, cudaFuncAttributeMaxDynamicSharedMemorySize, P1_SMEM);
    cudaFuncSetAttribute(p2_kernel, cudaFuncAttributeMaxDynamicSharedMemorySize, P2_SMEM);
    cudaFuncSetAttribute(attn_kernel, cudaFuncAttributeMaxDynamicSharedMemorySize, ATT_SMEM);

    prep_kernel<<<dim3(512, 6), 256>>>(S);
    p1_kernel<<<dim3(64, 3), 256, P1_SMEM>>>(A1);
    p2_kernel<<<dim3(64, 2, 3), 512, P2_SMEM>>>(A2);
    attn_kernel<<<dim3(16, 8, 4), 128, ATT_SMEM>>>(mask);
    outproj_kernel<<<128, 256>>>(Wo, bo, out);
}